// round 15
// baseline (speedup 1.0000x reference)
#include <cuda_runtime.h>
#include <cuda_bf16.h>
#include <math.h>

#define Bb   4
#define Cc   128
#define DI   256
#define Nn   16
#define Rr   8
#define Kk   4
#define Hh   48
#define Ww   48
#define LL   2304
#define BL   9216

typedef unsigned long long u64t;
union F2U { u64t v; float s[2]; float2 f; };

__device__ __forceinline__ u64t pk2(float lo, float hi){
    u64t r; asm("mov.b64 %0, {%1, %2};" : "=l"(r) : "f"(lo), "f"(hi)); return r;
}
__device__ __forceinline__ u64t fma2(u64t a, u64t b, u64t c){
    u64t r; asm("fma.rn.f32x2 %0, %1, %2, %3;" : "=l"(r) : "l"(a), "l"(b), "l"(c)); return r;
}
__device__ __forceinline__ u64t mul2(u64t a, u64t b){
    u64t r; asm("mul.rn.f32x2 %0, %1, %2;" : "=l"(r) : "l"(a), "l"(b)); return r;
}
__device__ __forceinline__ u64t add2(u64t a, u64t b){
    u64t r; asm("add.rn.f32x2 %0, %1, %2;" : "=l"(r) : "l"(a), "l"(b)); return r;
}
__device__ __forceinline__ u64t shfl64(u64t v, int m){
    F2U t; t.v = v;
    t.s[0] = __shfl_xor_sync(0xffffffffu, t.s[0], m);
    t.s[1] = __shfl_xor_sync(0xffffffffu, t.s[1], m);
    return t.v;
}
__device__ __forceinline__ float ex2f(float x){
    float r; asm("ex2.approx.f32 %0, %1;" : "=f"(r) : "f"(x)); return r;
}
__device__ __forceinline__ float sigmf(float x){
    return 1.f / (1.f + __expf(-x));
}

// ---------------- scratch ----------------
__device__ float g_xn   [(size_t)BL * Cc];
__device__ float g_xz   [(size_t)BL * 2 * DI];
__device__ float g_xhw  [(size_t)Bb * DI * LL];
__device__ float g_xwh  [(size_t)Bb * DI * LL];
__device__ float g_delta[(size_t)Bb * Kk * DI * LL];
__device__ float g_Bm   [(size_t)Bb * Kk * Nn * LL];
__device__ float g_Cm   [(size_t)Bb * Kk * Nn * LL];
__device__ float g_ys   [(size_t)Bb * Kk * DI * LL];
__device__ float g_ycomb[(size_t)BL * DI];
__device__ float g_yact [(size_t)BL * DI];

// ================= K0: channel LayerNorm -> xn (B*L, C) =================
__global__ void k0_ln(const float* __restrict__ x,
                      const float* __restrict__ lg, const float* __restrict__ lb)
{
    int b = blockIdx.x / Hh;
    int h = blockIdx.x % Hh;
    __shared__ float s[Cc][Ww + 1];
    __shared__ float mu[Ww], rs[Ww];

    const float* xb = x + (size_t)b * Cc * LL + (size_t)h * Ww;
    for (int idx = threadIdx.x; idx < Cc * Ww; idx += 256) {
        int c = idx / Ww, w = idx % Ww;
        s[c][w] = xb[(size_t)c * LL + w];
    }
    __syncthreads();
    if (threadIdx.x < Ww) {
        int w = threadIdx.x;
        float sm = 0.f, sq = 0.f;
        #pragma unroll 8
        for (int c = 0; c < Cc; c++) { float v = s[c][w]; sm += v; sq += v * v; }
        float m = sm * (1.f / Cc);
        float var = sq * (1.f / Cc) - m * m;
        mu[w] = m; rs[w] = rsqrtf(var + 1e-5f);
    }
    __syncthreads();
    float* out = g_xn + ((size_t)(b * LL + h * Ww)) * Cc;
    for (int idx = threadIdx.x; idx < Ww * Cc; idx += 256) {
        int w = idx >> 7, c = idx & 127;
        out[idx] = (s[c][w] - mu[w]) * rs[w] * lg[c] + lb[c];
    }
}

// ================= K1: xz = xn @ in_proj_w^T (f32x2 micro) =================
__global__ void __launch_bounds__(256) k1_gemm(const float* __restrict__ Wp)
{
    __shared__ float As[16][128];
    __shared__ float Bs[16][128];
    int m0 = blockIdx.x * 128, n0 = blockIdx.y * 128;
    int tid = threadIdx.x;
    int tm = tid & 15, tn = tid >> 4;
    int row = tid >> 1, kq = (tid & 1) * 8;
    u64t acc2[8][4];
    #pragma unroll
    for (int i = 0; i < 8; i++)
        #pragma unroll
        for (int j = 0; j < 4; j++) acc2[i][j] = 0ULL;

    for (int k0 = 0; k0 < Cc; k0 += 16) {
        float4 a0 = *(const float4*)(g_xn + (size_t)(m0 + row) * Cc + k0 + kq);
        float4 a1 = *(const float4*)(g_xn + (size_t)(m0 + row) * Cc + k0 + kq + 4);
        float4 b0 = *(const float4*)(Wp   + (size_t)(n0 + row) * Cc + k0 + kq);
        float4 b1 = *(const float4*)(Wp   + (size_t)(n0 + row) * Cc + k0 + kq + 4);
        __syncthreads();
        As[kq+0][row]=a0.x; As[kq+1][row]=a0.y; As[kq+2][row]=a0.z; As[kq+3][row]=a0.w;
        As[kq+4][row]=a1.x; As[kq+5][row]=a1.y; As[kq+6][row]=a1.z; As[kq+7][row]=a1.w;
        Bs[kq+0][row]=b0.x; Bs[kq+1][row]=b0.y; Bs[kq+2][row]=b0.z; Bs[kq+3][row]=b0.w;
        Bs[kq+4][row]=b1.x; Bs[kq+5][row]=b1.y; Bs[kq+6][row]=b1.z; Bs[kq+7][row]=b1.w;
        __syncthreads();
        #pragma unroll
        for (int kk = 0; kk < 16; kk++) {
            float4 av0 = *(const float4*)&As[kk][tm << 3];
            float4 av1 = *(const float4*)&As[kk][(tm << 3) + 4];
            ulonglong2 bq0 = *(const ulonglong2*)&Bs[kk][tn << 3];
            ulonglong2 bq1 = *(const ulonglong2*)&Bs[kk][(tn << 3) + 4];
            u64t b2[4] = {bq0.x, bq0.y, bq1.x, bq1.y};
            float am[8] = {av0.x,av0.y,av0.z,av0.w,av1.x,av1.y,av1.z,av1.w};
            #pragma unroll
            for (int i = 0; i < 8; i++) {
                u64t a2 = pk2(am[i], am[i]);
                #pragma unroll
                for (int j = 0; j < 4; j++)
                    acc2[i][j] = fma2(a2, b2[j], acc2[i][j]);
            }
        }
    }
    #pragma unroll
    for (int i = 0; i < 8; i++) {
        float* o = g_xz + (size_t)(m0 + (tm << 3) + i) * 512 + n0 + (tn << 3);
        ulonglong2 s0 = make_ulonglong2(acc2[i][0], acc2[i][1]);
        ulonglong2 s1 = make_ulonglong2(acc2[i][2], acc2[i][3]);
        *(ulonglong2*)o       = s0;
        *(ulonglong2*)(o + 4) = s1;
    }
}

// ================= K2: depthwise conv3x3 + bias + SiLU -> x_hw, x_wh =================
__global__ void k2_conv(const float* __restrict__ cw, const float* __restrict__ cb)
{
    int bi  = blockIdx.x;
    int dci = bi & 15;
    int hci = (bi >> 4) % 6;
    int b   = bi / 96;
    int d0  = dci * 16;
    int hc  = hci * 8;
    int tid = threadIdx.x;

    __shared__ float sbuf[10][Ww][17];
    __shared__ float wgt[16][9];
    __shared__ float bia[16];

    if (tid < 144) wgt[tid / 9][tid % 9] = cw[(size_t)(d0 + tid / 9) * 9 + tid % 9];
    if (tid >= 144 && tid < 160) bia[tid - 144] = cb[d0 + tid - 144];

    for (int idx = tid; idx < 10 * Ww * 16; idx += 256) {
        int d = idx & 15;
        int rest = idx >> 4;
        int w = rest % Ww;
        int hh = rest / Ww;
        int gh = hc - 1 + hh;
        float v = 0.f;
        if (gh >= 0 && gh < Hh)
            v = g_xz[((size_t)(b * LL + gh * Ww + w)) * 512 + d0 + d];
        sbuf[hh][w][d] = v;
    }
    __syncthreads();

    float outv[24];
    #pragma unroll
    for (int it = 0; it < 24; it++) {
        int idx = tid + it * 256;
        int d = idx / 384;
        int r = idx % 384;
        int h = r / Ww;
        int w = r % Ww;
        float sum = bia[d];
        #pragma unroll
        for (int i = 0; i < 3; i++) {
            #pragma unroll
            for (int j = 0; j < 3; j++) {
                int ww = w + j - 1;
                float xv = (ww >= 0 && ww < Ww) ? sbuf[h + i][ww][d] : 0.f;
                sum = fmaf(wgt[d][i * 3 + j], xv, sum);
            }
        }
        outv[it] = sum * sigmf(sum);
    }
    __syncthreads();
    #pragma unroll
    for (int it = 0; it < 24; it++) {
        int idx = tid + it * 256;
        int d = idx / 384; int r = idx % 384; int h = r / Ww; int w = r % Ww;
        g_xhw[((size_t)(b * DI + d0 + d)) * LL + (hc + h) * Ww + w] = outv[it];
        sbuf[h][w][d] = outv[it];
    }
    __syncthreads();
    for (int it = 0; it < 24; it++) {
        int idx = tid + it * 256;
        int d = idx / 384; int r = idx % 384; int w = r >> 3; int h = r & 7;
        g_xwh[((size_t)(b * DI + d0 + d)) * LL + w * Hh + hc + h] = sbuf[h][w][d];
    }
}

// ================= K3: x_proj + dt + softplus — 64-l tiles, dd-split halves =================
__global__ void __launch_bounds__(256) k3_xproj(const float* __restrict__ xpw,
                         const float* __restrict__ dtwg,
                         const float* __restrict__ dtbg)
{
    __shared__ float sm[2720 + 1536 + 2048];
    float* uT  = sm;            // [32][68]
    float* xd  = sm;            // [40][68] overlay (after GEMM)
    float* wp  = sm + 2720;     // [32][4][12]
    float* dtw = sm + 2720 + 1536;

    int lt = blockIdx.x % 36;
    int bk = blockIdx.x / 36;
    int k  = bk & 3;
    int b  = bk >> 2;
    int l0 = lt * 64;
    int tid = threadIdx.x;

    const float* usrc = (((k & 1) == 0) ? g_xhw : g_xwh) + (size_t)b * DI * LL;
    const bool rev = (k >= 2);

    for (int idx = tid; idx < DI * Rr; idx += 256)
        dtw[idx] = dtwg[(size_t)k * DI * Rr + idx];

    int lg    = tid & 31;
    int cg    = (tid >> 5) & 3;
    int dhalf = tid >> 7;

    u64t acc2[2][5];
    #pragma unroll
    for (int li = 0; li < 2; li++)
        #pragma unroll
        for (int jp = 0; jp < 5; jp++) acc2[li][jp] = 0ULL;

    int srow = tid >> 3;
    int scol = (tid & 7) * 8;

    for (int dc = 0; dc < DI; dc += 32) {
        __syncthreads();
        for (int idx = tid; idx < 1280; idx += 256) {
            int c = idx >> 5, dd = idx & 31;
            wp[dd * 48 + (c & 3) * 12 + (c >> 2)] = xpw[(size_t)(k * 40 + c) * DI + dc + dd];
        }
        {
            const float* urow = usrc + (size_t)(dc + srow) * LL;
            float* ud = uT + srow * 68;
            if (!rev) {
                float4 v0 = *(const float4*)(urow + l0 + scol);
                float4 v1 = *(const float4*)(urow + l0 + scol + 4);
                *(float4*)(ud + scol)     = v0;
                *(float4*)(ud + scol + 4) = v1;
            } else {
                float4 v0 = *(const float4*)(urow + (LL - 4 - l0 - scol));
                float4 v1 = *(const float4*)(urow + (LL - 8 - l0 - scol));
                *(float4*)(ud + scol)     = make_float4(v0.w, v0.z, v0.y, v0.x);
                *(float4*)(ud + scol + 4) = make_float4(v1.w, v1.z, v1.y, v1.x);
            }
        }
        __syncthreads();
        int db = dhalf * 16;
        #pragma unroll 4
        for (int dd = 0; dd < 16; dd++) {
            int dr = db + dd;
            F2U u2; u2.v = *(const u64t*)(uT + dr * 68 + lg * 2);
            u64t ua = pk2(u2.s[0], u2.s[0]);
            u64t ub = pk2(u2.s[1], u2.s[1]);
            const u64t* w64 = (const u64t*)(wp + dr * 48 + cg * 12);
            #pragma unroll
            for (int jp = 0; jp < 5; jp++) {
                u64t w2 = w64[jp];
                acc2[0][jp] = fma2(ua, w2, acc2[0][jp]);
                acc2[1][jp] = fma2(ub, w2, acc2[1][jp]);
            }
        }
    }
    __syncthreads();
    if (dhalf == 0) {
        #pragma unroll
        for (int jp = 0; jp < 5; jp++)
            #pragma unroll
            for (int li = 0; li < 2; li++) {
                F2U t; t.v = acc2[li][jp];
                xd[(cg + 8 * jp) * 68 + lg * 2 + li]     = t.s[0];
                xd[(cg + 8 * jp + 4) * 68 + lg * 2 + li] = t.s[1];
            }
    }
    __syncthreads();
    if (dhalf == 1) {
        #pragma unroll
        for (int jp = 0; jp < 5; jp++)
            #pragma unroll
            for (int li = 0; li < 2; li++) {
                F2U t; t.v = acc2[li][jp];
                xd[(cg + 8 * jp) * 68 + lg * 2 + li]     += t.s[0];
                xd[(cg + 8 * jp + 4) * 68 + lg * 2 + li] += t.s[1];
            }
    }
    __syncthreads();

    for (int idx = tid; idx < Nn * 64; idx += 256) {
        int nn = idx >> 6, li = idx & 63;
        g_Bm[((size_t)bk * Nn + nn) * LL + l0 + li] = xd[(Rr + nn) * 68 + li];
        g_Cm[((size_t)bk * Nn + nn) * LL + l0 + li] = xd[(Rr + Nn + nn) * 68 + li];
    }

    int l = tid & 63, q = tid >> 6;
    u64t dtr2[4];
    #pragma unroll
    for (int r = 0; r < 4; r++)
        dtr2[r] = pk2(xd[(2 * r) * 68 + l], xd[(2 * r + 1) * 68 + l]);

    const float* dtb = dtbg + k * DI;
    #pragma unroll 2
    for (int dd = 0; dd < 64; dd++) {
        int d = (q << 6) + dd;
        ulonglong2 wq0 = *(const ulonglong2*)(dtw + d * 8);
        ulonglong2 wq1 = *(const ulonglong2*)(dtw + d * 8 + 4);
        u64t m = fma2(wq0.x, dtr2[0],
                  fma2(wq0.y, dtr2[1],
                   fma2(wq1.x, dtr2[2],
                    mul2(wq1.y, dtr2[3]))));
        F2U t; t.v = m;
        float a = dtb[d] + t.s[0] + t.s[1];
        float sp = fmaxf(a, 0.f) + __logf(1.f + __expf(-fabsf(a)));
        g_delta[((size_t)bk * DI + d) * LL + l0 + l] = sp;
    }
}

// ================= K4: selective scan — software-pipelined reduce tree =================
__global__ void __launch_bounds__(128) k4_scan(const float* __restrict__ A_logs)
{
    int dg = blockIdx.x & 31;
    int bk = blockIdx.x >> 5;
    int k  = bk & 3;
    int b  = bk >> 2;
    int tid  = threadIdx.x;
    int lane = tid & 31;
    int warp = tid >> 5;
    int half = lane >> 4;
    int n    = lane & 15;
    int d    = dg * 8 + warp * 2 + half;

    float aa = -expf(A_logs[((size_t)(k * DI + d)) * Nn + n]) * 1.44269504088896f;
    u64t aa2 = pk2(aa, aa);

    const float* dp = g_delta + ((size_t)bk * DI + d) * LL;
    const float* up = ((((k & 1) == 0) ? g_xhw : g_xwh)) + ((size_t)(b * DI + d)) * LL;
    const float* Bg = g_Bm + (size_t)bk * Nn * LL;
    const float* Cg = g_Cm + (size_t)bk * Nn * LL;
    const bool rev = (k >= 2);

    int m2 = (((lane >> 3) & 1) << 1) | ((lane >> 2) & 1);
    bool wlane = ((lane & 3) == 0);

    __shared__ float sB[Nn][66];
    __shared__ float sC[Nn][66];
    __shared__ float yb[4][2][64];

    int crow = tid >> 3;
    int ccol = (tid & 7) * 8;

    float h = 0.f;

#define LOADDU(T, Dq0,Dq1,Uq0,Uq1)                                             \
    {   int _t = (T);                                                          \
        Dq0 = *(const float4*)(dp + _t); Dq1 = *(const float4*)(dp + _t + 4);  \
        if (!rev) { Uq0 = *(const float4*)(up + _t); Uq1 = *(const float4*)(up + _t + 4); } \
        else {                                                                 \
            float4 p0 = *(const float4*)(up + (LL - 8 - _t));                  \
            float4 p1 = *(const float4*)(up + (LL - 4 - _t));                  \
            Uq0.x = p1.w; Uq0.y = p1.z; Uq0.z = p1.y; Uq0.w = p1.x;            \
            Uq1.x = p0.w; Uq1.y = p0.z; Uq1.z = p0.y; Uq1.w = p0.x; } }

// packed tree over 16 lanes (bits 8,4,2,1), pairs along t; writes yb slot
#define TREE(P, SLOT) {                                                        \
    u64t t0_ = add2(P[0], shfl64(P[0], 8));                                    \
    u64t t1_ = add2(P[1], shfl64(P[1], 8));                                    \
    u64t t2_ = add2(P[2], shfl64(P[2], 8));                                    \
    u64t t3_ = add2(P[3], shfl64(P[3], 8));                                    \
    u64t qa_ = (lane & 8) ? t2_ : t0_;                                         \
    u64t qb_ = (lane & 8) ? t3_ : t1_;                                         \
    qa_ = add2(qa_, shfl64(qa_, 4));                                           \
    qb_ = add2(qb_, shfl64(qb_, 4));                                           \
    u64t r_ = (lane & 4) ? qb_ : qa_;                                          \
    r_ = add2(r_, shfl64(r_, 2));                                              \
    r_ = add2(r_, shfl64(r_, 1));                                              \
    if (wlane) { F2U tu_; tu_.v = r_;                                          \
        *(float2*)&yb[warp][half][(SLOT) + 2 * m2] = tu_.f; } }

    float4 D0, D1, U0, U1;
    LOADDU(0, D0, D1, U0, U1)

    for (int s0 = 0; s0 < LL; s0 += 64) {
        if (s0) __syncthreads();
        {
            float4 b0 = *(const float4*)(Bg + (size_t)crow * LL + s0 + ccol);
            float4 b1 = *(const float4*)(Bg + (size_t)crow * LL + s0 + ccol + 4);
            float4 c0 = *(const float4*)(Cg + (size_t)crow * LL + s0 + ccol);
            float4 c1 = *(const float4*)(Cg + (size_t)crow * LL + s0 + ccol + 4);
            float2* db = (float2*)&sB[crow][0];
            float2* dc = (float2*)&sC[crow][0];
            int p0 = ccol >> 1;
            db[p0+0] = make_float2(b0.x, b0.y); db[p0+1] = make_float2(b0.z, b0.w);
            db[p0+2] = make_float2(b1.x, b1.y); db[p0+3] = make_float2(b1.z, b1.w);
            dc[p0+0] = make_float2(c0.x, c0.y); dc[p0+1] = make_float2(c0.z, c0.w);
            dc[p0+2] = make_float2(c1.x, c1.y); dc[p0+3] = make_float2(c1.z, c1.w);
        }
        __syncthreads();

        u64t p2p[4];                 // deferred tree operands (previous chunk)
        #pragma unroll 2
        for (int c8 = 0; c8 < 64; c8 += 8) {
            int t0 = s0 + c8;
            int tn = t0 + 8;
            if (tn >= LL) tn = 0;
            float4 nD0, nD1, nU0, nU1;
            LOADDU(tn, nD0, nD1, nU0, nU1)

            F2U dl2[4], uu2[4];
            dl2[0].f = make_float2(D0.x, D0.y); dl2[1].f = make_float2(D0.z, D0.w);
            dl2[2].f = make_float2(D1.x, D1.y); dl2[3].f = make_float2(D1.z, D1.w);
            uu2[0].f = make_float2(U0.x, U0.y); uu2[1].f = make_float2(U0.z, U0.w);
            uu2[2].f = make_float2(U1.x, U1.y); uu2[3].f = make_float2(U1.z, U1.w);

            const u64t* b64 = (const u64t*)&sB[n][0];
            const u64t* c64 = (const u64t*)&sC[n][0];
            int pb = c8 >> 1;

            F2U ee[4], gg[4];
            u64t cc[4];
            #pragma unroll
            for (int j = 0; j < 4; j++) {
                ee[j].v = mul2(dl2[j].v, aa2);
                gg[j].v = mul2(mul2(dl2[j].v, uu2[j].v), b64[pb + j]);
                cc[j]   = c64[pb + j];
            }
            u64t p2c[4];
            #pragma unroll
            for (int j = 0; j < 4; j++) {
                float e0 = ex2f(ee[j].s[0]);
                float e1 = ex2f(ee[j].s[1]);
                h = fmaf(h, e0, gg[j].s[0]);
                float pa = h;
                h = fmaf(h, e1, gg[j].s[1]);
                p2c[j] = mul2(pk2(pa, h), cc[j]);
            }
            // deferred tree of the PREVIOUS chunk — independent chain, same
            // basic block: scheduler interleaves it with the work above.
            if (c8) TREE(p2p, c8 - 8)
            #pragma unroll
            for (int j = 0; j < 4; j++) p2p[j] = p2c[j];

            D0 = nD0; D1 = nD1; U0 = nU0; U1 = nU1;
        }
        TREE(p2p, 56)

        __syncwarp();
        {
            int idx = lane * 4, hs = idx >> 6, off = idx & 63;
            float4 v = *(float4*)&yb[warp][hs][off];
            *(float4*)(g_ys + ((size_t)bk * DI + dg * 8 + warp * 2 + hs) * LL + s0 + off) = v;
        }
        __syncwarp();
    }
#undef LOADDU
#undef TREE
}

// ================= K5: combine 4 directions + D*u terms =================
__global__ void k5_combine(const float* __restrict__ Ds)
{
    int hc = blockIdx.x % 6;
    int dc = (blockIdx.x / 6) & 15;
    int b  = blockIdx.x / 96;
    int d0 = dc * 16, h0 = hc * 8;
    __shared__ float s[16][392];
    __shared__ float sD02[16], sD13[16];
    int tid = threadIdx.x;
    const float* y0 = g_ys + ((size_t)(b * 4 + 0) * DI + d0) * LL;
    const float* y1 = g_ys + ((size_t)(b * 4 + 1) * DI + d0) * LL;
    const float* y2 = g_ys + ((size_t)(b * 4 + 2) * DI + d0) * LL;
    const float* y3 = g_ys + ((size_t)(b * 4 + 3) * DI + d0) * LL;
    const float* xh = g_xhw + ((size_t)(b * DI + d0)) * LL;
    const float* xw = g_xwh + ((size_t)(b * DI + d0)) * LL;
    int base = h0 * Ww;

    if (tid < 16) {
        sD02[tid] = Ds[0 * DI + d0 + tid] + Ds[2 * DI + d0 + tid];
        sD13[tid] = Ds[1 * DI + d0 + tid] + Ds[3 * DI + d0 + tid];
    }
    __syncthreads();

    for (int idx = tid; idx < 16 * 384; idx += 256) {
        int d = idx / 384, p = idx % 384;
        int l = base + p;
        s[d][p] = y0[(size_t)d * LL + l] + y2[(size_t)d * LL + (LL - 1 - l)]
                + sD02[d] * xh[(size_t)d * LL + l];
    }
    __syncthreads();
    for (int idx = tid; idx < 16 * 384; idx += 256) {
        int d = idx / 384, p = idx % 384;
        int w = p >> 3, hh = p & 7;
        int t1 = w * Hh + h0 + hh;
        float v = y1[(size_t)d * LL + t1] + y3[(size_t)d * LL + (LL - 1 - t1)]
                + sD13[d] * xw[(size_t)d * LL + t1];
        s[d][hh * Ww + w] += v;
    }
    __syncthreads();
    for (int idx = tid; idx < 384 * 16; idx += 256) {
        int p = idx >> 4, d = idx & 15;
        g_ycomb[((size_t)(b * LL + base + p)) * DI + d0 + d] = s[d][p];
    }
}

// ================= K6: LayerNorm(DI) + SiLU(z) gate =================
__global__ void k6_lngate(const float* __restrict__ og, const float* __restrict__ ob)
{
    int m = blockIdx.x;
    int tid = threadIdx.x;
    float v = g_ycomb[(size_t)m * DI + tid];
    float sm = v, sq = v * v;
    #pragma unroll
    for (int o = 16; o; o >>= 1) {
        sm += __shfl_xor_sync(0xffffffffu, sm, o);
        sq += __shfl_xor_sync(0xffffffffu, sq, o);
    }
    __shared__ float rs1[8], rs2[8];
    int w = tid >> 5, ln = tid & 31;
    if (ln == 0) { rs1[w] = sm; rs2[w] = sq; }
    __syncthreads();
    float ts = 0.f, tq = 0.f;
    #pragma unroll
    for (int i = 0; i < 8; i++) { ts += rs1[i]; tq += rs2[i]; }
    float mean = ts * (1.f / DI);
    float var  = tq * (1.f / DI) - mean * mean;
    float rstd = rsqrtf(var + 1e-5f);
    float zv = g_xz[(size_t)m * 512 + DI + tid];
    float gate = zv * sigmf(zv);
    g_yact[(size_t)m * DI + tid] = ((v - mean) * rstd * og[tid] + ob[tid]) * gate;
}

// ================= K7: out = x + (yact @ out_proj_w^T) (f32x2) =================
__global__ void __launch_bounds__(256) k7_out(const float* __restrict__ Wout,
                                              const float* __restrict__ x,
                                              float* __restrict__ out)
{
    int b  = blockIdx.z;
    int c0 = blockIdx.x * 64;
    int l0 = blockIdx.y * 128;
    __shared__ float As[16][64];
    __shared__ float Bs[16][128];
    int tid = threadIdx.x;
    int tm = tid & 15, tn = tid >> 4;
    int arow = tid >> 2, akq = (tid & 3) * 4;
    int brow = tid >> 1, bkq = (tid & 1) * 8;
    u64t acc2[4][4];
    #pragma unroll
    for (int i = 0; i < 4; i++)
        #pragma unroll
        for (int j = 0; j < 4; j++) acc2[i][j] = 0ULL;

    const float* Y = g_yact + (size_t)b * LL * DI;
    for (int k0 = 0; k0 < DI; k0 += 16) {
        float4 a0 = *(const float4*)(Wout + (size_t)(c0 + arow) * DI + k0 + akq);
        float4 b0 = *(const float4*)(Y + (size_t)(l0 + brow) * DI + k0 + bkq);
        float4 b1 = *(const float4*)(Y + (size_t)(l0 + brow) * DI + k0 + bkq + 4);
        __syncthreads();
        As[akq+0][arow]=a0.x; As[akq+1][arow]=a0.y; As[akq+2][arow]=a0.z; As[akq+3][arow]=a0.w;
        Bs[bkq+0][brow]=b0.x; Bs[bkq+1][brow]=b0.y; Bs[bkq+2][brow]=b0.z; Bs[bkq+3][brow]=b0.w;
        Bs[bkq+4][brow]=b1.x; Bs[bkq+5][brow]=b1.y; Bs[bkq+6][brow]=b1.z; Bs[bkq+7][brow]=b1.w;
        __syncthreads();
        #pragma unroll
        for (int kk = 0; kk < 16; kk++) {
            float4 av  = *(const float4*)&As[kk][tm << 2];
            ulonglong2 bq0 = *(const ulonglong2*)&Bs[kk][tn << 3];
            ulonglong2 bq1 = *(const ulonglong2*)&Bs[kk][(tn << 3) + 4];
            u64t b2[4] = {bq0.x, bq0.y, bq1.x, bq1.y};
            float am[4] = {av.x, av.y, av.z, av.w};
            #pragma unroll
            for (int i = 0; i < 4; i++) {
                u64t a2 = pk2(am[i], am[i]);
                #pragma unroll
                for (int j = 0; j < 4; j++)
                    acc2[i][j] = fma2(a2, b2[j], acc2[i][j]);
            }
        }
    }
    #pragma unroll
    for (int i = 0; i < 4; i++) {
        int c = c0 + (tm << 2) + i;
        size_t off = ((size_t)b * Cc + c) * LL + l0 + (tn << 3);
        ulonglong2 x0 = *(const ulonglong2*)(x + off);
        ulonglong2 x1 = *(const ulonglong2*)(x + off + 4);
        ulonglong2 s0 = make_ulonglong2(add2(acc2[i][0], x0.x), add2(acc2[i][1], x0.y));
        ulonglong2 s1 = make_ulonglong2(add2(acc2[i][2], x1.x), add2(acc2[i][3], x1.y));
        *(ulonglong2*)(out + off)     = s0;
        *(ulonglong2*)(out + off + 4) = s1;
    }
}

extern "C" void kernel_launch(void* const* d_in, const int* in_sizes, int n_in,
                              void* d_out, int out_size)
{
    const float* x          = (const float*)d_in[0];
    const float* ln1_g      = (const float*)d_in[1];
    const float* ln1_b      = (const float*)d_in[2];
    const float* in_proj_w  = (const float*)d_in[3];
    const float* conv_w     = (const float*)d_in[4];
    const float* conv_b     = (const float*)d_in[5];
    const float* x_proj_w   = (const float*)d_in[6];
    const float* dt_w       = (const float*)d_in[7];
    const float* dt_b       = (const float*)d_in[8];
    const float* A_logs     = (const float*)d_in[9];
    const float* Ds         = (const float*)d_in[10];
    const float* outn_g     = (const float*)d_in[11];
    const float* outn_b     = (const float*)d_in[12];
    const float* out_proj_w = (const float*)d_in[13];
    float* out = (float*)d_out;

    k0_ln<<<Bb * Hh, 256>>>(x, ln1_g, ln1_b);
    { dim3 g(BL / 128, 512 / 128); k1_gemm<<<g, 256>>>(in_proj_w); }
    k2_conv<<<Bb * 6 * 16, 256>>>(conv_w, conv_b);
    k3_xproj<<<Bb * Kk * 36, 256>>>(x_proj_w, dt_w, dt_b);
    k4_scan<<<32 * 16, 128>>>(A_logs);
    k5_combine<<<Bb * 16 * 6, 256>>>(Ds);
    k6_lngate<<<BL, 256>>>(outn_g, outn_b);
    { dim3 g(2, 18, Bb); k7_out<<<g, 256>>>(out_proj_w, x, out); }
}

// round 16
// speedup vs baseline: 1.0297x; 1.0297x over previous
#include <cuda_runtime.h>
#include <cuda_bf16.h>
#include <math.h>

#define Bb   4
#define Cc   128
#define DI   256
#define Nn   16
#define Rr   8
#define Kk   4
#define Hh   48
#define Ww   48
#define LL   2304
#define BL   9216

typedef unsigned long long u64t;
union F2U { u64t v; float s[2]; float2 f; };

__device__ __forceinline__ u64t pk2(float lo, float hi){
    u64t r; asm("mov.b64 %0, {%1, %2};" : "=l"(r) : "f"(lo), "f"(hi)); return r;
}
__device__ __forceinline__ u64t fma2(u64t a, u64t b, u64t c){
    u64t r; asm("fma.rn.f32x2 %0, %1, %2, %3;" : "=l"(r) : "l"(a), "l"(b), "l"(c)); return r;
}
__device__ __forceinline__ u64t mul2(u64t a, u64t b){
    u64t r; asm("mul.rn.f32x2 %0, %1, %2;" : "=l"(r) : "l"(a), "l"(b)); return r;
}
__device__ __forceinline__ u64t add2(u64t a, u64t b){
    u64t r; asm("add.rn.f32x2 %0, %1, %2;" : "=l"(r) : "l"(a), "l"(b)); return r;
}
__device__ __forceinline__ u64t shfl64(u64t v, int m){
    F2U t; t.v = v;
    t.s[0] = __shfl_xor_sync(0xffffffffu, t.s[0], m);
    t.s[1] = __shfl_xor_sync(0xffffffffu, t.s[1], m);
    return t.v;
}
__device__ __forceinline__ float ex2f(float x){
    float r; asm("ex2.approx.f32 %0, %1;" : "=f"(r) : "f"(x)); return r;
}
__device__ __forceinline__ float sigmf(float x){
    return 1.f / (1.f + __expf(-x));
}

// ---------------- scratch ----------------
__device__ float g_xn   [(size_t)BL * Cc];
__device__ float g_xz   [(size_t)BL * 2 * DI];
__device__ float g_xhw  [(size_t)Bb * DI * LL];
__device__ float g_xwh  [(size_t)Bb * DI * LL];
__device__ float g_delta[(size_t)Bb * Kk * DI * LL];
__device__ float g_Bm   [(size_t)Bb * Kk * Nn * LL];
__device__ float g_Cm   [(size_t)Bb * Kk * Nn * LL];
__device__ float g_ys   [(size_t)Bb * Kk * DI * LL];
__device__ float g_ycomb[(size_t)BL * DI];
__device__ float g_yact [(size_t)BL * DI];

// ================= K0: channel LayerNorm -> xn (B*L, C) =================
__global__ void k0_ln(const float* __restrict__ x,
                      const float* __restrict__ lg, const float* __restrict__ lb)
{
    int b = blockIdx.x / Hh;
    int h = blockIdx.x % Hh;
    __shared__ float s[Cc][Ww + 1];
    __shared__ float mu[Ww], rs[Ww];

    const float* xb = x + (size_t)b * Cc * LL + (size_t)h * Ww;
    for (int idx = threadIdx.x; idx < Cc * Ww; idx += 256) {
        int c = idx / Ww, w = idx % Ww;
        s[c][w] = xb[(size_t)c * LL + w];
    }
    __syncthreads();
    if (threadIdx.x < Ww) {
        int w = threadIdx.x;
        float sm = 0.f, sq = 0.f;
        #pragma unroll 8
        for (int c = 0; c < Cc; c++) { float v = s[c][w]; sm += v; sq += v * v; }
        float m = sm * (1.f / Cc);
        float var = sq * (1.f / Cc) - m * m;
        mu[w] = m; rs[w] = rsqrtf(var + 1e-5f);
    }
    __syncthreads();
    float* out = g_xn + ((size_t)(b * LL + h * Ww)) * Cc;
    for (int idx = threadIdx.x; idx < Ww * Cc; idx += 256) {
        int w = idx >> 7, c = idx & 127;
        out[idx] = (s[c][w] - mu[w]) * rs[w] * lg[c] + lb[c];
    }
}

// ================= K1: xz = xn @ in_proj_w^T (f32x2 micro) =================
__global__ void __launch_bounds__(256) k1_gemm(const float* __restrict__ Wp)
{
    __shared__ float As[16][128];
    __shared__ float Bs[16][128];
    int m0 = blockIdx.x * 128, n0 = blockIdx.y * 128;
    int tid = threadIdx.x;
    int tm = tid & 15, tn = tid >> 4;
    int row = tid >> 1, kq = (tid & 1) * 8;
    u64t acc2[8][4];
    #pragma unroll
    for (int i = 0; i < 8; i++)
        #pragma unroll
        for (int j = 0; j < 4; j++) acc2[i][j] = 0ULL;

    for (int k0 = 0; k0 < Cc; k0 += 16) {
        float4 a0 = *(const float4*)(g_xn + (size_t)(m0 + row) * Cc + k0 + kq);
        float4 a1 = *(const float4*)(g_xn + (size_t)(m0 + row) * Cc + k0 + kq + 4);
        float4 b0 = *(const float4*)(Wp   + (size_t)(n0 + row) * Cc + k0 + kq);
        float4 b1 = *(const float4*)(Wp   + (size_t)(n0 + row) * Cc + k0 + kq + 4);
        __syncthreads();
        As[kq+0][row]=a0.x; As[kq+1][row]=a0.y; As[kq+2][row]=a0.z; As[kq+3][row]=a0.w;
        As[kq+4][row]=a1.x; As[kq+5][row]=a1.y; As[kq+6][row]=a1.z; As[kq+7][row]=a1.w;
        Bs[kq+0][row]=b0.x; Bs[kq+1][row]=b0.y; Bs[kq+2][row]=b0.z; Bs[kq+3][row]=b0.w;
        Bs[kq+4][row]=b1.x; Bs[kq+5][row]=b1.y; Bs[kq+6][row]=b1.z; Bs[kq+7][row]=b1.w;
        __syncthreads();
        #pragma unroll
        for (int kk = 0; kk < 16; kk++) {
            float4 av0 = *(const float4*)&As[kk][tm << 3];
            float4 av1 = *(const float4*)&As[kk][(tm << 3) + 4];
            ulonglong2 bq0 = *(const ulonglong2*)&Bs[kk][tn << 3];
            ulonglong2 bq1 = *(const ulonglong2*)&Bs[kk][(tn << 3) + 4];
            u64t b2[4] = {bq0.x, bq0.y, bq1.x, bq1.y};
            float am[8] = {av0.x,av0.y,av0.z,av0.w,av1.x,av1.y,av1.z,av1.w};
            #pragma unroll
            for (int i = 0; i < 8; i++) {
                u64t a2 = pk2(am[i], am[i]);
                #pragma unroll
                for (int j = 0; j < 4; j++)
                    acc2[i][j] = fma2(a2, b2[j], acc2[i][j]);
            }
        }
    }
    #pragma unroll
    for (int i = 0; i < 8; i++) {
        float* o = g_xz + (size_t)(m0 + (tm << 3) + i) * 512 + n0 + (tn << 3);
        ulonglong2 s0 = make_ulonglong2(acc2[i][0], acc2[i][1]);
        ulonglong2 s1 = make_ulonglong2(acc2[i][2], acc2[i][3]);
        *(ulonglong2*)o       = s0;
        *(ulonglong2*)(o + 4) = s1;
    }
}

// ================= K2: depthwise conv3x3 + bias + SiLU -> x_hw, x_wh =================
__global__ void k2_conv(const float* __restrict__ cw, const float* __restrict__ cb)
{
    int bi  = blockIdx.x;
    int dci = bi & 15;
    int hci = (bi >> 4) % 6;
    int b   = bi / 96;
    int d0  = dci * 16;
    int hc  = hci * 8;
    int tid = threadIdx.x;

    __shared__ float sbuf[10][Ww][17];
    __shared__ float wgt[16][9];
    __shared__ float bia[16];

    if (tid < 144) wgt[tid / 9][tid % 9] = cw[(size_t)(d0 + tid / 9) * 9 + tid % 9];
    if (tid >= 144 && tid < 160) bia[tid - 144] = cb[d0 + tid - 144];

    for (int idx = tid; idx < 10 * Ww * 16; idx += 256) {
        int d = idx & 15;
        int rest = idx >> 4;
        int w = rest % Ww;
        int hh = rest / Ww;
        int gh = hc - 1 + hh;
        float v = 0.f;
        if (gh >= 0 && gh < Hh)
            v = g_xz[((size_t)(b * LL + gh * Ww + w)) * 512 + d0 + d];
        sbuf[hh][w][d] = v;
    }
    __syncthreads();

    float outv[24];
    #pragma unroll
    for (int it = 0; it < 24; it++) {
        int idx = tid + it * 256;
        int d = idx / 384;
        int r = idx % 384;
        int h = r / Ww;
        int w = r % Ww;
        float sum = bia[d];
        #pragma unroll
        for (int i = 0; i < 3; i++) {
            #pragma unroll
            for (int j = 0; j < 3; j++) {
                int ww = w + j - 1;
                float xv = (ww >= 0 && ww < Ww) ? sbuf[h + i][ww][d] : 0.f;
                sum = fmaf(wgt[d][i * 3 + j], xv, sum);
            }
        }
        outv[it] = sum * sigmf(sum);
    }
    __syncthreads();
    #pragma unroll
    for (int it = 0; it < 24; it++) {
        int idx = tid + it * 256;
        int d = idx / 384; int r = idx % 384; int h = r / Ww; int w = r % Ww;
        g_xhw[((size_t)(b * DI + d0 + d)) * LL + (hc + h) * Ww + w] = outv[it];
        sbuf[h][w][d] = outv[it];
    }
    __syncthreads();
    for (int it = 0; it < 24; it++) {
        int idx = tid + it * 256;
        int d = idx / 384; int r = idx % 384; int w = r >> 3; int h = r & 7;
        g_xwh[((size_t)(b * DI + d0 + d)) * LL + w * Hh + hc + h] = sbuf[h][w][d];
    }
}

// ================= K3: x_proj + dt + softplus — 64-l tiles, dd-split halves =================
__global__ void __launch_bounds__(256) k3_xproj(const float* __restrict__ xpw,
                         const float* __restrict__ dtwg,
                         const float* __restrict__ dtbg)
{
    __shared__ float sm[2720 + 1536 + 2048];
    float* uT  = sm;            // [32][68]
    float* xd  = sm;            // [40][68] overlay (after GEMM)
    float* wp  = sm + 2720;     // [32][4][12]
    float* dtw = sm + 2720 + 1536;

    int lt = blockIdx.x % 36;
    int bk = blockIdx.x / 36;
    int k  = bk & 3;
    int b  = bk >> 2;
    int l0 = lt * 64;
    int tid = threadIdx.x;

    const float* usrc = (((k & 1) == 0) ? g_xhw : g_xwh) + (size_t)b * DI * LL;
    const bool rev = (k >= 2);

    for (int idx = tid; idx < DI * Rr; idx += 256)
        dtw[idx] = dtwg[(size_t)k * DI * Rr + idx];

    int lg    = tid & 31;
    int cg    = (tid >> 5) & 3;
    int dhalf = tid >> 7;

    u64t acc2[2][5];
    #pragma unroll
    for (int li = 0; li < 2; li++)
        #pragma unroll
        for (int jp = 0; jp < 5; jp++) acc2[li][jp] = 0ULL;

    int srow = tid >> 3;
    int scol = (tid & 7) * 8;

    for (int dc = 0; dc < DI; dc += 32) {
        __syncthreads();
        for (int idx = tid; idx < 1280; idx += 256) {
            int c = idx >> 5, dd = idx & 31;
            wp[dd * 48 + (c & 3) * 12 + (c >> 2)] = xpw[(size_t)(k * 40 + c) * DI + dc + dd];
        }
        {
            const float* urow = usrc + (size_t)(dc + srow) * LL;
            float* ud = uT + srow * 68;
            if (!rev) {
                float4 v0 = *(const float4*)(urow + l0 + scol);
                float4 v1 = *(const float4*)(urow + l0 + scol + 4);
                *(float4*)(ud + scol)     = v0;
                *(float4*)(ud + scol + 4) = v1;
            } else {
                float4 v0 = *(const float4*)(urow + (LL - 4 - l0 - scol));
                float4 v1 = *(const float4*)(urow + (LL - 8 - l0 - scol));
                *(float4*)(ud + scol)     = make_float4(v0.w, v0.z, v0.y, v0.x);
                *(float4*)(ud + scol + 4) = make_float4(v1.w, v1.z, v1.y, v1.x);
            }
        }
        __syncthreads();
        int db = dhalf * 16;
        #pragma unroll 4
        for (int dd = 0; dd < 16; dd++) {
            int dr = db + dd;
            F2U u2; u2.v = *(const u64t*)(uT + dr * 68 + lg * 2);
            u64t ua = pk2(u2.s[0], u2.s[0]);
            u64t ub = pk2(u2.s[1], u2.s[1]);
            const u64t* w64 = (const u64t*)(wp + dr * 48 + cg * 12);
            #pragma unroll
            for (int jp = 0; jp < 5; jp++) {
                u64t w2 = w64[jp];
                acc2[0][jp] = fma2(ua, w2, acc2[0][jp]);
                acc2[1][jp] = fma2(ub, w2, acc2[1][jp]);
            }
        }
    }
    __syncthreads();
    if (dhalf == 0) {
        #pragma unroll
        for (int jp = 0; jp < 5; jp++)
            #pragma unroll
            for (int li = 0; li < 2; li++) {
                F2U t; t.v = acc2[li][jp];
                xd[(cg + 8 * jp) * 68 + lg * 2 + li]     = t.s[0];
                xd[(cg + 8 * jp + 4) * 68 + lg * 2 + li] = t.s[1];
            }
    }
    __syncthreads();
    if (dhalf == 1) {
        #pragma unroll
        for (int jp = 0; jp < 5; jp++)
            #pragma unroll
            for (int li = 0; li < 2; li++) {
                F2U t; t.v = acc2[li][jp];
                xd[(cg + 8 * jp) * 68 + lg * 2 + li]     += t.s[0];
                xd[(cg + 8 * jp + 4) * 68 + lg * 2 + li] += t.s[1];
            }
    }
    __syncthreads();

    for (int idx = tid; idx < Nn * 64; idx += 256) {
        int nn = idx >> 6, li = idx & 63;
        g_Bm[((size_t)bk * Nn + nn) * LL + l0 + li] = xd[(Rr + nn) * 68 + li];
        g_Cm[((size_t)bk * Nn + nn) * LL + l0 + li] = xd[(Rr + Nn + nn) * 68 + li];
    }

    int l = tid & 63, q = tid >> 6;
    u64t dtr2[4];
    #pragma unroll
    for (int r = 0; r < 4; r++)
        dtr2[r] = pk2(xd[(2 * r) * 68 + l], xd[(2 * r + 1) * 68 + l]);

    const float* dtb = dtbg + k * DI;
    #pragma unroll 2
    for (int dd = 0; dd < 64; dd++) {
        int d = (q << 6) + dd;
        ulonglong2 wq0 = *(const ulonglong2*)(dtw + d * 8);
        ulonglong2 wq1 = *(const ulonglong2*)(dtw + d * 8 + 4);
        u64t m = fma2(wq0.x, dtr2[0],
                  fma2(wq0.y, dtr2[1],
                   fma2(wq1.x, dtr2[2],
                    mul2(wq1.y, dtr2[3]))));
        F2U t; t.v = m;
        float a = dtb[d] + t.s[0] + t.s[1];
        float sp = fmaxf(a, 0.f) + __logf(1.f + __expf(-fabsf(a)));
        g_delta[((size_t)bk * DI + d) * LL + l0 + l] = sp;
    }
}

// ================= K4: selective scan — depth-2 D/U prefetch + packed reduce tree =================
__global__ void __launch_bounds__(128) k4_scan(const float* __restrict__ A_logs)
{
    int dg = blockIdx.x & 31;
    int bk = blockIdx.x >> 5;
    int k  = bk & 3;
    int b  = bk >> 2;
    int tid  = threadIdx.x;
    int lane = tid & 31;
    int warp = tid >> 5;
    int half = lane >> 4;
    int n    = lane & 15;
    int d    = dg * 8 + warp * 2 + half;

    float aa = -expf(A_logs[((size_t)(k * DI + d)) * Nn + n]) * 1.44269504088896f;
    u64t aa2 = pk2(aa, aa);

    const float* dp = g_delta + ((size_t)bk * DI + d) * LL;
    const float* up = ((((k & 1) == 0) ? g_xhw : g_xwh)) + ((size_t)(b * DI + d)) * LL;
    const float* Bg = g_Bm + (size_t)bk * Nn * LL;
    const float* Cg = g_Cm + (size_t)bk * Nn * LL;
    const bool rev = (k >= 2);

    int m2 = (((lane >> 3) & 1) << 1) | ((lane >> 2) & 1);
    bool wlane = ((lane & 3) == 0);

    __shared__ float sB[Nn][66];
    __shared__ float sC[Nn][66];
    __shared__ float yb[4][2][64];

    int crow = tid >> 3;
    int ccol = (tid & 7) * 8;

    float h = 0.f;

#define LOADDU(T, Dq0,Dq1,Uq0,Uq1)                                             \
    {   int _t = (T);                                                          \
        Dq0 = *(const float4*)(dp + _t); Dq1 = *(const float4*)(dp + _t + 4);  \
        if (!rev) { Uq0 = *(const float4*)(up + _t); Uq1 = *(const float4*)(up + _t + 4); } \
        else {                                                                 \
            float4 p0 = *(const float4*)(up + (LL - 8 - _t));                  \
            float4 p1 = *(const float4*)(up + (LL - 4 - _t));                  \
            Uq0.x = p1.w; Uq0.y = p1.z; Uq0.z = p1.y; Uq0.w = p1.x;            \
            Uq1.x = p0.w; Uq1.y = p0.z; Uq1.z = p0.y; Uq1.w = p0.x; } }

    // depth-2 pipeline: a = current chunk, bq = next chunk
    float4 aD0, aD1, aU0, aU1;
    float4 bD0, bD1, bU0, bU1;
    LOADDU(0, aD0, aD1, aU0, aU1)
    LOADDU(8, bD0, bD1, bU0, bU1)

    for (int s0 = 0; s0 < LL; s0 += 64) {
        if (s0) __syncthreads();
        {
            float4 b0 = *(const float4*)(Bg + (size_t)crow * LL + s0 + ccol);
            float4 b1 = *(const float4*)(Bg + (size_t)crow * LL + s0 + ccol + 4);
            float4 c0 = *(const float4*)(Cg + (size_t)crow * LL + s0 + ccol);
            float4 c1 = *(const float4*)(Cg + (size_t)crow * LL + s0 + ccol + 4);
            float2* db = (float2*)&sB[crow][0];
            float2* dc = (float2*)&sC[crow][0];
            int p0 = ccol >> 1;
            db[p0+0] = make_float2(b0.x, b0.y); db[p0+1] = make_float2(b0.z, b0.w);
            db[p0+2] = make_float2(b1.x, b1.y); db[p0+3] = make_float2(b1.z, b1.w);
            dc[p0+0] = make_float2(c0.x, c0.y); dc[p0+1] = make_float2(c0.z, c0.w);
            dc[p0+2] = make_float2(c1.x, c1.y); dc[p0+3] = make_float2(c1.z, c1.w);
        }
        __syncthreads();

        #pragma unroll 2
        for (int c8 = 0; c8 < 64; c8 += 8) {
            int t0 = s0 + c8;
            int t2 = t0 + 16;                  // load two chunks ahead
            if (t2 >= LL) t2 = 0;              // clamped (discarded) prefetch
            float4 nD0, nD1, nU0, nU1;
            LOADDU(t2, nD0, nD1, nU0, nU1)

            F2U dl2[4], uu2[4];
            dl2[0].f = make_float2(aD0.x, aD0.y); dl2[1].f = make_float2(aD0.z, aD0.w);
            dl2[2].f = make_float2(aD1.x, aD1.y); dl2[3].f = make_float2(aD1.z, aD1.w);
            uu2[0].f = make_float2(aU0.x, aU0.y); uu2[1].f = make_float2(aU0.z, aU0.w);
            uu2[2].f = make_float2(aU1.x, aU1.y); uu2[3].f = make_float2(aU1.z, aU1.w);

            const u64t* b64 = (const u64t*)&sB[n][0];
            const u64t* c64 = (const u64t*)&sC[n][0];
            int pb = c8 >> 1;

            F2U ee[4], gg[4];
            u64t cc[4];
            #pragma unroll
            for (int j = 0; j < 4; j++) {
                ee[j].v = mul2(dl2[j].v, aa2);
                gg[j].v = mul2(mul2(dl2[j].v, uu2[j].v), b64[pb + j]);
                cc[j]   = c64[pb + j];
            }
            u64t p2[4];
            #pragma unroll
            for (int j = 0; j < 4; j++) {
                float e0 = ex2f(ee[j].s[0]);
                float e1 = ex2f(ee[j].s[1]);
                h = fmaf(h, e0, gg[j].s[0]);
                float pa = h;
                h = fmaf(h, e1, gg[j].s[1]);
                p2[j] = mul2(pk2(pa, h), cc[j]);
            }
            #pragma unroll
            for (int j = 0; j < 4; j++) p2[j] = add2(p2[j], shfl64(p2[j], 8));
            u64t qa = (lane & 8) ? p2[2] : p2[0];
            u64t qb = (lane & 8) ? p2[3] : p2[1];
            qa = add2(qa, shfl64(qa, 4));
            qb = add2(qb, shfl64(qb, 4));
            u64t r = (lane & 4) ? qb : qa;
            r = add2(r, shfl64(r, 2));
            r = add2(r, shfl64(r, 1));
            if (wlane) {
                F2U t; t.v = r;
                *(float2*)&yb[warp][half][c8 + 2 * m2] = t.f;
            }

            // rotate pipeline
            aD0 = bD0; aD1 = bD1; aU0 = bU0; aU1 = bU1;
            bD0 = nD0; bD1 = nD1; bU0 = nU0; bU1 = nU1;
        }
        __syncwarp();
        {
            int idx = lane * 4, hs = idx >> 6, off = idx & 63;
            float4 v = *(float4*)&yb[warp][hs][off];
            *(float4*)(g_ys + ((size_t)bk * DI + dg * 8 + warp * 2 + hs) * LL + s0 + off) = v;
        }
        __syncwarp();
    }
#undef LOADDU
}

// ================= K5: combine 4 directions + D*u terms =================
__global__ void k5_combine(const float* __restrict__ Ds)
{
    int hc = blockIdx.x % 6;
    int dc = (blockIdx.x / 6) & 15;
    int b  = blockIdx.x / 96;
    int d0 = dc * 16, h0 = hc * 8;
    __shared__ float s[16][392];
    __shared__ float sD02[16], sD13[16];
    int tid = threadIdx.x;
    const float* y0 = g_ys + ((size_t)(b * 4 + 0) * DI + d0) * LL;
    const float* y1 = g_ys + ((size_t)(b * 4 + 1) * DI + d0) * LL;
    const float* y2 = g_ys + ((size_t)(b * 4 + 2) * DI + d0) * LL;
    const float* y3 = g_ys + ((size_t)(b * 4 + 3) * DI + d0) * LL;
    const float* xh = g_xhw + ((size_t)(b * DI + d0)) * LL;
    const float* xw = g_xwh + ((size_t)(b * DI + d0)) * LL;
    int base = h0 * Ww;

    if (tid < 16) {
        sD02[tid] = Ds[0 * DI + d0 + tid] + Ds[2 * DI + d0 + tid];
        sD13[tid] = Ds[1 * DI + d0 + tid] + Ds[3 * DI + d0 + tid];
    }
    __syncthreads();

    for (int idx = tid; idx < 16 * 384; idx += 256) {
        int d = idx / 384, p = idx % 384;
        int l = base + p;
        s[d][p] = y0[(size_t)d * LL + l] + y2[(size_t)d * LL + (LL - 1 - l)]
                + sD02[d] * xh[(size_t)d * LL + l];
    }
    __syncthreads();
    for (int idx = tid; idx < 16 * 384; idx += 256) {
        int d = idx / 384, p = idx % 384;
        int w = p >> 3, hh = p & 7;
        int t1 = w * Hh + h0 + hh;
        float v = y1[(size_t)d * LL + t1] + y3[(size_t)d * LL + (LL - 1 - t1)]
                + sD13[d] * xw[(size_t)d * LL + t1];
        s[d][hh * Ww + w] += v;
    }
    __syncthreads();
    for (int idx = tid; idx < 384 * 16; idx += 256) {
        int p = idx >> 4, d = idx & 15;
        g_ycomb[((size_t)(b * LL + base + p)) * DI + d0 + d] = s[d][p];
    }
}

// ================= K6: LayerNorm(DI) + SiLU(z) gate =================
__global__ void k6_lngate(const float* __restrict__ og, const float* __restrict__ ob)
{
    int m = blockIdx.x;
    int tid = threadIdx.x;
    float v = g_ycomb[(size_t)m * DI + tid];
    float sm = v, sq = v * v;
    #pragma unroll
    for (int o = 16; o; o >>= 1) {
        sm += __shfl_xor_sync(0xffffffffu, sm, o);
        sq += __shfl_xor_sync(0xffffffffu, sq, o);
    }
    __shared__ float rs1[8], rs2[8];
    int w = tid >> 5, ln = tid & 31;
    if (ln == 0) { rs1[w] = sm; rs2[w] = sq; }
    __syncthreads();
    float ts = 0.f, tq = 0.f;
    #pragma unroll
    for (int i = 0; i < 8; i++) { ts += rs1[i]; tq += rs2[i]; }
    float mean = ts * (1.f / DI);
    float var  = tq * (1.f / DI) - mean * mean;
    float rstd = rsqrtf(var + 1e-5f);
    float zv = g_xz[(size_t)m * 512 + DI + tid];
    float gate = zv * sigmf(zv);
    g_yact[(size_t)m * DI + tid] = ((v - mean) * rstd * og[tid] + ob[tid]) * gate;
}

// ================= K7: out = x + (yact @ out_proj_w^T) (f32x2) =================
__global__ void __launch_bounds__(256) k7_out(const float* __restrict__ Wout,
                                              const float* __restrict__ x,
                                              float* __restrict__ out)
{
    int b  = blockIdx.z;
    int c0 = blockIdx.x * 64;
    int l0 = blockIdx.y * 128;
    __shared__ float As[16][64];
    __shared__ float Bs[16][128];
    int tid = threadIdx.x;
    int tm = tid & 15, tn = tid >> 4;
    int arow = tid >> 2, akq = (tid & 3) * 4;
    int brow = tid >> 1, bkq = (tid & 1) * 8;
    u64t acc2[4][4];
    #pragma unroll
    for (int i = 0; i < 4; i++)
        #pragma unroll
        for (int j = 0; j < 4; j++) acc2[i][j] = 0ULL;

    const float* Y = g_yact + (size_t)b * LL * DI;
    for (int k0 = 0; k0 < DI; k0 += 16) {
        float4 a0 = *(const float4*)(Wout + (size_t)(c0 + arow) * DI + k0 + akq);
        float4 b0 = *(const float4*)(Y + (size_t)(l0 + brow) * DI + k0 + bkq);
        float4 b1 = *(const float4*)(Y + (size_t)(l0 + brow) * DI + k0 + bkq + 4);
        __syncthreads();
        As[akq+0][arow]=a0.x; As[akq+1][arow]=a0.y; As[akq+2][arow]=a0.z; As[akq+3][arow]=a0.w;
        Bs[bkq+0][brow]=b0.x; Bs[bkq+1][brow]=b0.y; Bs[bkq+2][brow]=b0.z; Bs[bkq+3][brow]=b0.w;
        Bs[bkq+4][brow]=b1.x; Bs[bkq+5][brow]=b1.y; Bs[bkq+6][brow]=b1.z; Bs[bkq+7][brow]=b1.w;
        __syncthreads();
        #pragma unroll
        for (int kk = 0; kk < 16; kk++) {
            float4 av  = *(const float4*)&As[kk][tm << 2];
            ulonglong2 bq0 = *(const ulonglong2*)&Bs[kk][tn << 3];
            ulonglong2 bq1 = *(const ulonglong2*)&Bs[kk][(tn << 3) + 4];
            u64t b2[4] = {bq0.x, bq0.y, bq1.x, bq1.y};
            float am[4] = {av.x, av.y, av.z, av.w};
            #pragma unroll
            for (int i = 0; i < 4; i++) {
                u64t a2 = pk2(am[i], am[i]);
                #pragma unroll
                for (int j = 0; j < 4; j++)
                    acc2[i][j] = fma2(a2, b2[j], acc2[i][j]);
            }
        }
    }
    #pragma unroll
    for (int i = 0; i < 4; i++) {
        int c = c0 + (tm << 2) + i;
        size_t off = ((size_t)b * Cc + c) * LL + l0 + (tn << 3);
        ulonglong2 x0 = *(const ulonglong2*)(x + off);
        ulonglong2 x1 = *(const ulonglong2*)(x + off + 4);
        ulonglong2 s0 = make_ulonglong2(add2(acc2[i][0], x0.x), add2(acc2[i][1], x0.y));
        ulonglong2 s1 = make_ulonglong2(add2(acc2[i][2], x1.x), add2(acc2[i][3], x1.y));
        *(ulonglong2*)(out + off)     = s0;
        *(ulonglong2*)(out + off + 4) = s1;
    }
}

extern "C" void kernel_launch(void* const* d_in, const int* in_sizes, int n_in,
                              void* d_out, int out_size)
{
    const float* x          = (const float*)d_in[0];
    const float* ln1_g      = (const float*)d_in[1];
    const float* ln1_b      = (const float*)d_in[2];
    const float* in_proj_w  = (const float*)d_in[3];
    const float* conv_w     = (const float*)d_in[4];
    const float* conv_b     = (const float*)d_in[5];
    const float* x_proj_w   = (const float*)d_in[6];
    const float* dt_w       = (const float*)d_in[7];
    const float* dt_b       = (const float*)d_in[8];
    const float* A_logs     = (const float*)d_in[9];
    const float* Ds         = (const float*)d_in[10];
    const float* outn_g     = (const float*)d_in[11];
    const float* outn_b     = (const float*)d_in[12];
    const float* out_proj_w = (const float*)d_in[13];
    float* out = (float*)d_out;

    k0_ln<<<Bb * Hh, 256>>>(x, ln1_g, ln1_b);
    { dim3 g(BL / 128, 512 / 128); k1_gemm<<<g, 256>>>(in_proj_w); }
    k2_conv<<<Bb * 6 * 16, 256>>>(conv_w, conv_b);
    k3_xproj<<<Bb * Kk * 36, 256>>>(x_proj_w, dt_w, dt_b);
    k4_scan<<<32 * 16, 128>>>(A_logs);
    k5_combine<<<Bb * 16 * 6, 256>>>(Ds);
    k6_lngate<<<BL, 256>>>(outn_g, outn_b);
    { dim3 g(2, 18, Bb); k7_out<<<g, 256>>>(out_proj_w, x, out); }
}